// round 17
// baseline (speedup 1.0000x reference)
#include <cuda_runtime.h>
#include <cstdint>
#include <cstddef>

#define T_STEPS 1024
#define BATCH   8
#define DIM     1024
#define NSLOTS  8
#define RANK    256
#define GROUP   16            // CTAs per slot group (= cluster size)
#define NCTAS   (NSLOTS*GROUP)

#define SV_STRIDE  68          // V chunk: [256 r][64 d]   (17 float4)
#define SU_STRIDE  260         // U chunk: [64 d][256 r]   (65 float4)
#define SH_STRIDE  68          // own h:   [8 b][64 d]
#define SVH_STRIDE 260         // full Vh: [8 b][256 r]

#define SV_ELEMS   (256*SV_STRIDE)   // 17408
#define SU_ELEMS   (64*SU_STRIDE)    // 16640
#define SH_ELEMS   (8*SH_STRIDE)     // 544
#define SVH_ELEMS  (8*SVH_STRIDE)    // 2080
#define SRED_ELEMS 4096
#define SMEM_FLOATS (SV_ELEMS+SU_ELEMS+SH_ELEMS+SVH_ELEMS+SRED_ELEMS)
#define SMEM_BYTES  (SMEM_FLOATS*4)  // 163072 B < 227KB

// ---------------- device scratch (static, allocation-rule-safe) ----------------
__device__ float    g_wx[(size_t)T_STEPS*BATCH*DIM];   // Wx + bias, [t][b][d]
__device__ float    g_vh3[3*NSLOTS*BATCH*RANK];        // triple-buffered Vh accum [buf][s][b][r]
__device__ unsigned g_barA[NSLOTS];                    // group-A monotonic barrier
__device__ unsigned g_barB[NSLOTS];                    // group-B barrier (fallback path)

// packed fp32x2 FMA (full-rate fp32 on sm_103a; 3-reg FFMA is half rate)
__device__ __forceinline__ float2 ffma2(float2 a, float2 b, float2 c) {
    float2 d;
    asm("fma.rn.f32x2 %0, %1, %2, %3;"
        : "=l"(*reinterpret_cast<unsigned long long*>(&d))
        : "l"(*reinterpret_cast<const unsigned long long*>(&a)),
          "l"(*reinterpret_cast<const unsigned long long*>(&b)),
          "l"(*reinterpret_cast<const unsigned long long*>(&c)));
    return d;
}
__device__ __forceinline__ float2 lo2(float4 v) { return make_float2(v.x, v.y); }
__device__ __forceinline__ float2 hi2(float4 v) { return make_float2(v.z, v.w); }

// ======================= kernel 1: Wx = x @ W^T + bias =======================
__global__ __launch_bounds__(256) void wx_kernel(const float* __restrict__ x,
                                                 const float* __restrict__ W,
                                                 const float* __restrict__ bias) {
    __shared__ float sA[64*36];
    __shared__ float sB[64*36];
    const int tid = threadIdx.x;
    const int m0 = blockIdx.y * 64;
    const int n0 = blockIdx.x * 64;
    if (blockIdx.x == 0 && blockIdx.y == 0 && tid < NSLOTS) {
        g_barA[tid] = 0u; g_barB[tid] = 0u;
    }
    if (blockIdx.y == 0) {                // 16 CTAs x 256 thr zero the Vh buffers
        int base = blockIdx.x * 256 + tid;
        #pragma unroll
        for (int k = 0; k < 12; k++) g_vh3[base + k*4096] = 0.f;
    }

    const int tm = tid >> 4;
    const int tn = tid & 15;

    float2 acc[4][4];
    #pragma unroll
    for (int i = 0; i < 4; i++)
        #pragma unroll
        for (int j = 0; j < 4; j++) acc[i][j] = make_float2(0.f, 0.f);

    for (int kb = 0; kb < 1024; kb += 32) {
        __syncthreads();
        #pragma unroll
        for (int it = 0; it < 2; it++) {
            int i = tid + it*256;
            int row = i >> 3, c4 = (i & 7) * 4;
            *(float4*)&sA[row*36 + c4] = *(const float4*)&x[(size_t)(m0+row)*1024 + kb + c4];
            *(float4*)&sB[row*36 + c4] = *(const float4*)&W[(size_t)(n0+row)*1024 + kb + c4];
        }
        __syncthreads();
        #pragma unroll
        for (int kk = 0; kk < 32; kk += 4) {
            float4 a[4], b[4];
            #pragma unroll
            for (int i = 0; i < 4; i++) a[i] = *(float4*)&sA[(tm+16*i)*36 + kk];
            #pragma unroll
            for (int j = 0; j < 4; j++) b[j] = *(float4*)&sB[(tn+16*j)*36 + kk];
            #pragma unroll
            for (int i = 0; i < 4; i++)
                #pragma unroll
                for (int j = 0; j < 4; j++) {
                    acc[i][j] = ffma2(lo2(a[i]), lo2(b[j]), acc[i][j]);
                    acc[i][j] = ffma2(hi2(a[i]), hi2(b[j]), acc[i][j]);
                }
        }
    }
    #pragma unroll
    for (int i = 0; i < 4; i++) {
        int m = m0 + tm + 16*i;
        #pragma unroll
        for (int j = 0; j < 4; j++) {
            int n = n0 + tn + 16*j;
            g_wx[(size_t)m*1024 + n] = acc[i][j].x + acc[i][j].y + bias[n];
        }
    }
}

// ================== kernel 2: persistent recurrence, batch-split pipelined ==================
// 128 CTAs = 8 slots x 16 d-chunks, 256 threads. Each step splits the batch into
// A (b 0-3) and B (b 4-7). A uses a software counter barrier, B uses the SPLIT
// cluster barrier (arrive early, wait late) so each group's comm drain and
// rendezvous hides under the other group's GEMM compute.
template <bool USE_CLUSTER>
__global__ void __launch_bounds__(256, 1)
recur_kernel_t(const float* __restrict__ h0, const float* __restrict__ U,
               const float* __restrict__ V, float* __restrict__ hout) {
    extern __shared__ float sm[];
    float* sV   = sm;                    // [256][SV_STRIDE]
    float* sU   = sV  + SV_ELEMS;        // [64][SU_STRIDE]
    float* sH   = sU  + SU_ELEMS;        // [8][SH_STRIDE]
    float* sVh  = sH  + SH_ELEMS;        // [8][SVH_STRIDE]
    float* sRed = sVh + SVH_ELEMS;       // 4096 floats scratch

    const int tid  = threadIdx.x;
    const int lane = tid & 31;
    const int w    = tid >> 5;
    const int s    = blockIdx.x >> 4;
    const int rk   = blockIdx.x & 15;
    const int dlo  = rk * 64;

    // resident weights (float4)
    #pragma unroll
    for (int k = 0; k < 16; k++) {
        int i = tid + k*256;
        int row = i >> 4, c4 = (i & 15) * 4;
        *(float4*)&sV[row*SV_STRIDE + c4] =
            *(const float4*)&V[((size_t)(s*256 + row))*1024 + dlo + c4];
    }
    #pragma unroll
    for (int k = 0; k < 16; k++) {
        int i = tid + k*256;
        int row = i >> 6, c4 = (i & 63) * 4;
        *(float4*)&sU[row*SU_STRIDE + c4] =
            *(const float4*)&U[((size_t)(s*1024 + dlo + row))*256 + c4];
    }
    for (int i = tid; i < 512; i += 256) {
        int b = i >> 6, dd = i & 63;
        float v = h0[(size_t)b*8192 + s*1024 + dlo + dd];
        sH[b*SH_STRIDE + dd] = v;
        hout[(size_t)s*8192 + b*1024 + dlo + dd] = v;
    }

    // GEMM1 map: 128 r-threads (r, r+128) x 2 d-halves of 32
    const int rt1 = tid & 127;
    const int dbase1 = (tid >> 7) * 32;
    const int ks1 = tid >> 7;
    // GEMM2 map: 32 d-threads (d, d+32) x 8 r-slices of 32 (slice = warp id)
    const int dt2 = tid & 31;
    const int ks2 = tid >> 5;
    // staging map: warp w stages r-slice [32w, 32w+32) of a 4-b group: lane -> (b, q)
    const int stb = lane >> 3;           // 0..3 within group
    const int stq = lane & 7;            // f4 quad within 32-r slice
    // epilogue map: thread -> (b = eb in A, eb+4 in B, d = edi)
    const int edi = tid & 63;
    const int eb  = tid >> 6;            // 0..3

    for (int t = 0; t < T_STEPS; t++) {
        const float* wxrow = g_wx + (size_t)t * 8192;
        float wxp0 = wxrow[(eb    )*1024 + dlo + edi];
        float wxp1 = wxrow[(eb + 4)*1024 + dlo + edi];

        __syncthreads();   // sH ready from prev epilogue; sRed free

        float* gbuf  = g_vh3 + ((size_t)(t % 3) * NSLOTS + s) * 2048;
        float* gbufA = gbuf;             // b 0-3: [4][256]
        float* gbufB = gbuf + 1024;      // b 4-7: [4][256]

        // ---- GEMM1_A (b 0-3) ----
        {
            float2 acc[2][4];
            #pragma unroll
            for (int i = 0; i < 2; i++)
                #pragma unroll
                for (int b = 0; b < 4; b++) acc[i][b] = make_float2(0.f, 0.f);
            #pragma unroll
            for (int dd = 0; dd < 32; dd += 4) {
                int d = dbase1 + dd;
                float4 v0 = *(float4*)&sV[rt1*SV_STRIDE + d];
                float4 v1 = *(float4*)&sV[(rt1+128)*SV_STRIDE + d];
                #pragma unroll
                for (int b = 0; b < 4; b++) {
                    float4 hh = *(float4*)&sH[b*SH_STRIDE + d];
                    acc[0][b] = ffma2(lo2(v0), lo2(hh), acc[0][b]);
                    acc[0][b] = ffma2(hi2(v0), hi2(hh), acc[0][b]);
                    acc[1][b] = ffma2(lo2(v1), lo2(hh), acc[1][b]);
                    acc[1][b] = ffma2(hi2(v1), hi2(hh), acc[1][b]);
                }
            }
            #pragma unroll
            for (int i = 0; i < 2; i++)
                #pragma unroll
                for (int b = 0; b < 4; b++)
                    sRed[ks1*1024 + b*256 + rt1 + 128*i] = acc[i][b].x + acc[i][b].y;
        }
        __syncthreads();

        // combine + RED publish group A (4 REDs/thread), then release-fence
        {
            #pragma unroll
            for (int k = 0; k < 4; k++) {
                int c = tid + k*256;           // 0..1023
                int b = c >> 8, r = c & 255;
                float v = sRed[b*256 + r] + sRed[1024 + b*256 + r];
                atomicAdd(&gbufA[b*256 + r], v);
            }
            __threadfence();                   // publish my REDs (for barA release)
        }

        // ---- GEMM1_B (b 4-7) — overlaps group A's drain/rendezvous ----
        {
            float2 acc[2][4];
            #pragma unroll
            for (int i = 0; i < 2; i++)
                #pragma unroll
                for (int b = 0; b < 4; b++) acc[i][b] = make_float2(0.f, 0.f);
            #pragma unroll
            for (int dd = 0; dd < 32; dd += 4) {
                int d = dbase1 + dd;
                float4 v0 = *(float4*)&sV[rt1*SV_STRIDE + d];
                float4 v1 = *(float4*)&sV[(rt1+128)*SV_STRIDE + d];
                #pragma unroll
                for (int b = 0; b < 4; b++) {
                    float4 hh = *(float4*)&sH[(b+4)*SH_STRIDE + d];
                    acc[0][b] = ffma2(lo2(v0), lo2(hh), acc[0][b]);
                    acc[0][b] = ffma2(hi2(v0), hi2(hh), acc[0][b]);
                    acc[1][b] = ffma2(lo2(v1), lo2(hh), acc[1][b]);
                    acc[1][b] = ffma2(hi2(v1), hi2(hh), acc[1][b]);
                }
            }
            #pragma unroll
            for (int i = 0; i < 2; i++)
                #pragma unroll
                for (int b = 0; b < 4; b++)
                    sRed[2048 + ks1*1024 + b*256 + rt1 + 128*i] = acc[i][b].x + acc[i][b].y;
        }
        __syncthreads();   // sRed_B ready AND every thread past its fence

        if (tid == 0) atomicAdd(&g_barA[s], 1u);   // group-A arrive

        // combine + RED publish group B
        {
            #pragma unroll
            for (int k = 0; k < 4; k++) {
                int c = tid + k*256;
                int b = c >> 8, r = c & 255;
                float v = sRed[2048 + b*256 + r] + sRed[3072 + b*256 + r];
                atomicAdd(&gbufB[b*256 + r], v);
            }
        }
        if (USE_CLUSTER) {
            asm volatile("barrier.cluster.arrive.aligned;" ::: "memory"); // release B
        } else {
            __threadfence();
            __syncthreads();
            if (tid == 0) atomicAdd(&g_barB[s], 1u);
        }

        // ---- wait group A (rendezvous largely overlapped by GEMM1_B) ----
        if (tid == 0) {
            unsigned target = (unsigned)GROUP * (unsigned)(t + 1);
            while (*((volatile unsigned*)&g_barA[s]) < target) { }
        }
        __syncthreads();

        // stage Vh_A warp-locally (warp w: r-slice [32w,32w+32), b 0-3); zero A(t+2)
        {
            const float4* src = (const float4*)gbufA;     // [4 b][64 f4]
            float4 v = __ldcg(&src[stb*64 + w*8 + stq]);
            *(float4*)&sVh[stb*SVH_STRIDE + (w*8 + stq)*4] = v;
            float* zbufA = g_vh3 + ((size_t)((t + 2) % 3) * NSLOTS + s) * 2048;
            *(float4*)&zbufA[tid*4] = make_float4(0.f, 0.f, 0.f, 0.f);  // zero whole A half? tid<256*4=1024 ✓ covers [0:1024)
            __syncwarp();
        }

        // ---- GEMM2_A (b 0-3) — overlaps group B's drain/rendezvous ----
        {
            float2 acc[2][4];
            #pragma unroll
            for (int i = 0; i < 2; i++)
                #pragma unroll
                for (int b = 0; b < 4; b++) acc[i][b] = make_float2(0.f, 0.f);
            const int rbase = ks2 * 32;
            #pragma unroll
            for (int rr = 0; rr < 32; rr += 4) {
                int r = rbase + rr;
                float4 u0 = *(float4*)&sU[dt2*SU_STRIDE + r];
                float4 u1 = *(float4*)&sU[(dt2+32)*SU_STRIDE + r];
                #pragma unroll
                for (int b = 0; b < 4; b++) {
                    float4 vh = *(float4*)&sVh[b*SVH_STRIDE + r];
                    acc[0][b] = ffma2(lo2(u0), lo2(vh), acc[0][b]);
                    acc[0][b] = ffma2(hi2(u0), hi2(vh), acc[0][b]);
                    acc[1][b] = ffma2(lo2(u1), lo2(vh), acc[1][b]);
                    acc[1][b] = ffma2(hi2(u1), hi2(vh), acc[1][b]);
                }
            }
            #pragma unroll
            for (int i = 0; i < 2; i++)
                #pragma unroll
                for (int b = 0; b < 4; b++)
                    sRed[ks2*256 + b*64 + dt2 + 32*i] = acc[i][b].x + acc[i][b].y;
        }

        // ---- wait group B ----
        if (USE_CLUSTER) {
            asm volatile("barrier.cluster.wait.aligned;" ::: "memory");  // acquire B
        } else {
            if (tid == 0) {
                unsigned target = (unsigned)GROUP * (unsigned)(t + 1);
                while (*((volatile unsigned*)&g_barB[s]) < target) { }
            }
            __syncthreads();
        }

        // stage Vh_B warp-locally; zero B half of buffer (t+2)
        {
            const float4* src = (const float4*)gbufB;     // [4 b][64 f4]
            float4 v = __ldcg(&src[stb*64 + w*8 + stq]);
            *(float4*)&sVh[(stb+4)*SVH_STRIDE + (w*8 + stq)*4] = v;
            float* zbufB = g_vh3 + ((size_t)((t + 2) % 3) * NSLOTS + s) * 2048 + 1024;
            if (tid < 256) *(float4*)&zbufB[tid*4] = make_float4(0.f, 0.f, 0.f, 0.f);
            __syncwarp();
        }

        // ---- GEMM2_B (b 4-7) ----
        {
            float2 acc[2][4];
            #pragma unroll
            for (int i = 0; i < 2; i++)
                #pragma unroll
                for (int b = 0; b < 4; b++) acc[i][b] = make_float2(0.f, 0.f);
            const int rbase = ks2 * 32;
            #pragma unroll
            for (int rr = 0; rr < 32; rr += 4) {
                int r = rbase + rr;
                float4 u0 = *(float4*)&sU[dt2*SU_STRIDE + r];
                float4 u1 = *(float4*)&sU[(dt2+32)*SU_STRIDE + r];
                #pragma unroll
                for (int b = 0; b < 4; b++) {
                    float4 vh = *(float4*)&sVh[(b+4)*SVH_STRIDE + r];
                    acc[0][b] = ffma2(lo2(u0), lo2(vh), acc[0][b]);
                    acc[0][b] = ffma2(hi2(u0), hi2(vh), acc[0][b]);
                    acc[1][b] = ffma2(lo2(u1), lo2(vh), acc[1][b]);
                    acc[1][b] = ffma2(hi2(u1), hi2(vh), acc[1][b]);
                }
            }
            #pragma unroll
            for (int i = 0; i < 2; i++)
                #pragma unroll
                for (int b = 0; b < 4; b++)
                    sRed[2048 + ks2*256 + b*64 + dt2 + 32*i] = acc[i][b].x + acc[i][b].y;
        }
        __syncthreads();   // sRed2A + sRed2B ready

        // epilogue: both groups; thread -> (eb, edi) in A and (eb+4, edi) in B
        {
            float* hdst = hout + ((size_t)(t+1)*8 + s)*8192;
            float uhA = 0.f, uhB = 0.f;
            #pragma unroll
            for (int k = 0; k < 8; k++) {
                uhA += sRed[k*256 + eb*64 + edi];
                uhB += sRed[2048 + k*256 + eb*64 + edi];
            }
            float hnA = tanhf(wxp0 + uhA);
            float hnB = tanhf(wxp1 + uhB);
            sH[(eb    )*SH_STRIDE + edi] = hnA;
            sH[(eb + 4)*SH_STRIDE + edi] = hnB;
            hdst[(eb    )*1024 + dlo + edi] = hnA;
            hdst[(eb + 4)*1024 + dlo + edi] = hnB;
        }
    }
}

// ============== kernel 3: out = (sum_s C_s h[t+1,s]) * silu(z) ==============
__global__ __launch_bounds__(256) void out_kernel(const float* __restrict__ z,
                                                  const float* __restrict__ C,
                                                  const float* __restrict__ hout,
                                                  float* __restrict__ out) {
    size_t idx = (size_t)blockIdx.x * 256 + threadIdx.x;
    int t   = (int)(idx >> 13);
    int rem = (int)(idx & 8191);
    float zz  = z[idx];
    float sig = 1.f / (1.f + expf(-zz));
    const float* hb = hout + ((size_t)(t+1))*65536 + rem;
    float acc = 0.f;
    #pragma unroll
    for (int s = 0; s < 8; s++) acc += C[s] * hb[(size_t)s*8192];
    out[idx] = acc * zz * sig;
}

// ================================ launch ================================
extern "C" void kernel_launch(void* const* d_in, const int* in_sizes, int n_in,
                              void* d_out, int out_size) {
    (void)in_sizes; (void)n_in; (void)out_size;
    const float* x    = (const float*)d_in[0];
    const float* z    = (const float*)d_in[1];
    const float* h0   = (const float*)d_in[2];
    const float* Wxm  = (const float*)d_in[3];
    const float* U    = (const float*)d_in[4];
    const float* V    = (const float*)d_in[5];
    const float* bias = (const float*)d_in[6];
    const float* C    = (const float*)d_in[7];

    float* out  = (float*)d_out;
    float* hout = out + (size_t)T_STEPS*BATCH*DIM;

    cudaFuncSetAttribute(recur_kernel_t<true>,
                         cudaFuncAttributeMaxDynamicSharedMemorySize, SMEM_BYTES);
    cudaFuncSetAttribute(recur_kernel_t<true>,
                         cudaFuncAttributeNonPortableClusterSizeAllowed, 1);
    cudaFuncSetAttribute(recur_kernel_t<false>,
                         cudaFuncAttributeMaxDynamicSharedMemorySize, SMEM_BYTES);

    dim3 wgrid(16, 128);
    wx_kernel<<<wgrid, 256>>>(x, Wxm, bias);

    cudaLaunchConfig_t cfg = {};
    cfg.gridDim          = dim3(NCTAS, 1, 1);
    cfg.blockDim         = dim3(256, 1, 1);
    cfg.dynamicSmemBytes = SMEM_BYTES;
    cudaLaunchAttribute attrs[1];
    attrs[0].id = cudaLaunchAttributeClusterDimension;
    attrs[0].val.clusterDim.x = GROUP;
    attrs[0].val.clusterDim.y = 1;
    attrs[0].val.clusterDim.z = 1;
    cfg.attrs    = attrs;
    cfg.numAttrs = 1;

    int maxClusters = 0;
    cudaError_t qe = cudaOccupancyMaxActiveClusters(&maxClusters,
                                                    recur_kernel_t<true>, &cfg);
    bool use_cluster = (qe == cudaSuccess && maxClusters >= NSLOTS);
    if (!use_cluster) (void)cudaGetLastError();

    if (use_cluster) {
        cudaError_t le = cudaLaunchKernelEx(&cfg, recur_kernel_t<true>,
                                            h0, U, V, hout);
        if (le != cudaSuccess) {
            (void)cudaGetLastError();
            use_cluster = false;
        }
    }
    if (!use_cluster) {
        recur_kernel_t<false><<<NCTAS, 256, SMEM_BYTES>>>(h0, U, V, hout);
    }

    out_kernel<<<32768, 256>>>(z, C, hout, out);
}